// round 1
// baseline (speedup 1.0000x reference)
#include <cuda_runtime.h>
#include <math.h>

#define Bz 64
#define Nn 196
#define Tt 32
#define Ss 31
#define VD 128
#define EM 256
#define AT 256
#define HD 512
#define VOC 30000
#define KX 384      // EM + VD
#define KG 896      // EM + VD + HD

// ---------------- scratch (device globals; no allocation) ----------------
__device__ float g_UV[Bz*Nn*AT];       // 12.8 MB
__device__ float g_X[Ss*Bz*EM];        // x_t used at step j = embed[y[:, j]]
__device__ float g_Wh[Bz*AT];
__device__ float g_h[2][Bz*HD];
__device__ float g_c[2][Bz*HD];
__device__ float g_ctx[Bz*VD];
__device__ float g_H[Ss*Bz*HD];        // all h_new states
__device__ float g_E[Ss*Bz*EM];        // e_t for all steps (1984 x 256)

// ---------------- packed f32x2 helpers ----------------
__device__ __forceinline__ unsigned long long pack2(float x, float y){
    unsigned long long r;
    asm("mov.b64 %0, {%1, %2};" : "=l"(r) : "f"(x), "f"(y));
    return r;
}
__device__ __forceinline__ float2 unpack2(unsigned long long v){
    float2 r;
    asm("mov.b64 {%0, %1}, %2;" : "=f"(r.x), "=f"(r.y) : "l"(v));
    return r;
}
__device__ __forceinline__ void fma2(unsigned long long& d, unsigned long long a, unsigned long long b){
    asm("fma.rn.f32x2 %0, %1, %2, %0;" : "+l"(d) : "l"(a), "l"(b));
}

__device__ __forceinline__ float sigf(float x){ return 1.0f/(1.0f + __expf(-x)); }

// ---------------- init: zero h0, c0 (globals persist across graph replays) ----------------
__global__ void init_kernel(){
    int i = blockIdx.x*256 + threadIdx.x;
    g_h[0][i] = 0.f;
    g_c[0][i] = 0.f;
}

// ---------------- gather: g_X[s][b][:] = embed[y[b,s]] for s=0..30 ----------------
__global__ void gather_kernel(const int* __restrict__ y, const float* __restrict__ embed){
    int s = blockIdx.x, b = blockIdx.y, e = threadIdx.x;
    int tok = y[b*Tt + s];
    g_X[(s*Bz + b)*EM + e] = embed[(size_t)tok*EM + e];
}

// ---------------- UV[b,n,a] = V[b,n,:] . Uw[a,:] + Ub[a] ----------------
__global__ void __launch_bounds__(256) uv_kernel(const float* __restrict__ V,
                                                 const float* __restrict__ Uw,
                                                 const float* __restrict__ Ub){
    int b = blockIdx.x;
    int n0 = blockIdx.y * 32;
    int tid = threadIdx.x;
    __shared__ float sV[32][VD];
    for (int e = tid; e < 32*VD; e += 256){
        int n = n0 + (e / VD);
        sV[e / VD][e % VD] = (n < Nn) ? V[((size_t)b*Nn + n)*VD + (e % VD)] : 0.f;
    }
    __syncthreads();
    int a = tid; // 0..255
    float acc[32];
    #pragma unroll
    for (int n = 0; n < 32; n++) acc[n] = 0.f;
    for (int kc = 0; kc < VD; kc += 16){
        float u[16];
        #pragma unroll
        for (int i = 0; i < 16; i += 4)
            *(float4*)&u[i] = *(const float4*)&Uw[a*VD + kc + i];
        #pragma unroll
        for (int n = 0; n < 32; n++){
            #pragma unroll
            for (int k = 0; k < 16; k++)
                acc[n] += u[k] * sV[n][kc + k];
        }
    }
    float ub = Ub[a];
    #pragma unroll
    for (int n = 0; n < 32; n++){
        int nn = n0 + n;
        if (nn < Nn) g_UV[((size_t)b*Nn + nn)*AT + a] = acc[n] + ub;
    }
}

// ---------------- Wh = h @ Ww.T + Wb : tile [8 b][32 a], grid (8,8) ----------------
__global__ void __launch_bounds__(256) wh_kernel(const float* __restrict__ Ww,
                                                 const float* __restrict__ Wb, int p){
    __shared__ float sh[8][HD];
    int tid = threadIdx.x;
    int b0 = blockIdx.x*8, a0 = blockIdx.y*32;
    const float* hp = g_h[p];
    for (int e = tid; e < 8*HD; e += 256)
        sh[e / HD][e % HD] = hp[(b0 + e / HD)*HD + (e % HD)];
    __syncthreads();
    int b_in = tid >> 5;
    int a = a0 + (tid & 31);
    const float4* w4 = (const float4*)(Ww + (size_t)a*HD);
    const float4* h4 = (const float4*)sh[b_in];
    float acc = 0.f;
    #pragma unroll 8
    for (int k = 0; k < HD/4; k++){
        float4 w = w4[k], hh = h4[k];
        acc += w.x*hh.x + w.y*hh.y + w.z*hh.z + w.w*hh.w;
    }
    g_Wh[(b0 + b_in)*AT + a] = acc + Wb[a];
}

// ---------------- attention: e, softmax, ctx. grid 64 (per b) ----------------
__global__ void __launch_bounds__(256) attn_kernel(const float* __restrict__ vw,
                                                   const float* __restrict__ vb,
                                                   const float* __restrict__ V){
    int b = blockIdx.x, tid = threadIdx.x;
    __shared__ float sWh[AT];
    __shared__ float sv[AT];
    __shared__ float se[Nn];
    __shared__ float sred[8];
    __shared__ float s_sc[2];
    sWh[tid] = g_Wh[b*AT + tid];
    sv[tid]  = vw[tid];
    __syncthreads();
    int warp = tid >> 5, lane = tid & 31;
    float vbias = vb[0];
    for (int n = warp; n < Nn; n += 8){
        const float* uvp = g_UV + ((size_t)b*Nn + n)*AT;
        float pz = 0.f;
        #pragma unroll
        for (int j = 0; j < 8; j++){
            int a = lane + j*32;
            pz += tanhf(sWh[a] + uvp[a]) * sv[a];
        }
        #pragma unroll
        for (int o = 16; o; o >>= 1) pz += __shfl_xor_sync(0xffffffffu, pz, o);
        if (lane == 0) se[n] = pz + vbias;
    }
    __syncthreads();
    // max
    float m = -1e30f;
    for (int n = tid; n < Nn; n += 256) m = fmaxf(m, se[n]);
    #pragma unroll
    for (int o = 16; o; o >>= 1) m = fmaxf(m, __shfl_xor_sync(0xffffffffu, m, o));
    if (lane == 0) sred[warp] = m;
    __syncthreads();
    if (tid == 0){
        float mm = sred[0];
        #pragma unroll
        for (int i = 1; i < 8; i++) mm = fmaxf(mm, sred[i]);
        s_sc[0] = mm;
    }
    __syncthreads();
    float mm = s_sc[0];
    float sum = 0.f;
    for (int n = tid; n < Nn; n += 256){
        float ex = __expf(se[n] - mm);
        se[n] = ex;
        sum += ex;
    }
    #pragma unroll
    for (int o = 16; o; o >>= 1) sum += __shfl_xor_sync(0xffffffffu, sum, o);
    if (lane == 0) sred[warp] = sum;
    __syncthreads();
    if (tid == 0){
        float s = 0.f;
        #pragma unroll
        for (int i = 0; i < 8; i++) s += sred[i];
        s_sc[1] = 1.0f / s;
    }
    __syncthreads();
    float inv = s_sc[1];
    if (tid < VD){
        float cv = 0.f;
        #pragma unroll 4
        for (int n = 0; n < Nn; n++)
            cv += se[n] * V[((size_t)b*Nn + n)*VD + tid];
        g_ctx[b*VD + tid] = cv * inv;
    }
}

// ---------------- LSTM gates GEMM + pointwise. tile [16 b][32 u x 4 gates], grid (4,16) ----------------
__global__ void __launch_bounds__(256) lstm_kernel(const float* __restrict__ Wih,
                                                   const float* __restrict__ Whh,
                                                   const float* __restrict__ bih,
                                                   const float* __restrict__ bhh,
                                                   int step, int p){
    __shared__ float sA[16][33];
    __shared__ float sWt[32][134];   // k-major: sWt[k][g*32 + uu]
    int tid = threadIdx.x;
    int b0 = blockIdx.x*16, u0 = blockIdx.y*32;
    int u2 = tid & 15, b_in = tid >> 4;      // b_in 0..15
    const float* hp = g_h[p];
    const float* xp = g_X + (size_t)step*Bz*EM;
    unsigned long long acc[4] = {0ull, 0ull, 0ull, 0ull};

    for (int kc = 0; kc < KG; kc += 32){
        // A tile: 16 b x 32 k
        {
            int row = tid >> 5, col = tid & 31;
            #pragma unroll
            for (int it = 0; it < 2; it++){
                int r = row + it*8;
                int bb = b0 + r;
                int k = kc + col;
                float v;
                if (k < EM)        v = xp[bb*EM + k];
                else if (k < KX)   v = g_ctx[bb*VD + (k - EM)];
                else               v = hp[bb*HD + (k - KX)];
                sA[r][col] = v;
            }
        }
        // W tile: 128 j x 32 k, stored k-major
        {
            int col = tid & 31;
            int row0 = tid >> 5;
            #pragma unroll
            for (int it = 0; it < 16; it++){
                int jrow = row0 + it*8;           // 0..127
                int g = jrow >> 5, uu = jrow & 31;
                int j = g*HD + u0 + uu;
                int k = kc + col;
                float w = (k < KX) ? Wih[(size_t)j*KX + k] : Whh[(size_t)j*HD + (k - KX)];
                sWt[col][jrow] = w;
            }
        }
        __syncthreads();
        #pragma unroll
        for (int k = 0; k < 32; k++){
            float av = sA[b_in][k];
            unsigned long long avd = pack2(av, av);
            #pragma unroll
            for (int g = 0; g < 4; g++){
                unsigned long long w2 = *(const unsigned long long*)&sWt[k][g*32 + u2*2];
                fma2(acc[g], avd, w2);
            }
        }
        __syncthreads();
    }

    int b = b0 + b_in;
    int ubase = u0 + u2*2;
    float2 ia = unpack2(acc[0]), fa = unpack2(acc[1]);
    float2 ga = unpack2(acc[2]), oa = unpack2(acc[3]);
    float2 hn2, cn2;
    #pragma unroll
    for (int s2 = 0; s2 < 2; s2++){
        int u = ubase + s2;
        float iv = (s2 ? ia.y : ia.x) + bih[u]        + bhh[u];
        float fv = (s2 ? fa.y : fa.x) + bih[HD + u]   + bhh[HD + u];
        float gv = (s2 ? ga.y : ga.x) + bih[2*HD + u] + bhh[2*HD + u];
        float ov = (s2 ? oa.y : oa.x) + bih[3*HD + u] + bhh[3*HD + u];
        float cprev = g_c[p][b*HD + u];
        float cn = sigf(fv)*cprev + sigf(iv)*tanhf(gv);
        float hn = sigf(ov)*tanhf(cn);
        if (s2){ cn2.y = cn; hn2.y = hn; } else { cn2.x = cn; hn2.x = hn; }
    }
    int q = p ^ 1;
    *(float2*)&g_c[q][b*HD + ubase] = cn2;
    *(float2*)&g_h[q][b*HD + ubase] = hn2;
    *(float2*)&g_H[((size_t)step*Bz + b)*HD + ubase] = hn2;
}

// ---------------- proj: Eall = Hall @ proj.T. tile [64 r][64 a], grid (31,4) ----------------
__global__ void __launch_bounds__(256) proj_kernel(const float* __restrict__ projw){
    __shared__ float sA[64][33];
    __shared__ float sW[64][33];
    int tid = threadIdx.x;
    int r0 = blockIdx.x*64, a0 = blockIdx.y*64;
    int tx = tid & 15, ty = tid >> 4;
    float acc[4][4] = {};
    for (int kc = 0; kc < HD; kc += 32){
        for (int e = tid; e < 64*32; e += 256){
            int row = e >> 5, col = e & 31;
            sA[row][col] = g_H[(size_t)(r0 + row)*HD + kc + col];
            sW[row][col] = projw[(size_t)(a0 + row)*HD + kc + col];
        }
        __syncthreads();
        #pragma unroll
        for (int k = 0; k < 32; k++){
            float af[4], wf[4];
            #pragma unroll
            for (int i = 0; i < 4; i++) af[i] = sA[ty*4 + i][k];
            #pragma unroll
            for (int j = 0; j < 4; j++) wf[j] = sW[tx*4 + j][k];
            #pragma unroll
            for (int i = 0; i < 4; i++)
                #pragma unroll
                for (int j = 0; j < 4; j++)
                    acc[i][j] += af[i]*wf[j];
        }
        __syncthreads();
    }
    #pragma unroll
    for (int i = 0; i < 4; i++)
        #pragma unroll
        for (int j = 0; j < 4; j++)
            g_E[(size_t)(r0 + ty*4 + i)*EM + a0 + tx*4 + j] = acc[i][j];
}

// ---------------- logits: [1984 x 30000] = g_E @ embed.T ; tile [64 r][128 v] ----------------
__global__ void __launch_bounds__(256) logit_kernel(const float* __restrict__ embed,
                                                    float* __restrict__ out){
    __shared__ float sAt[32][68];    // k-major A
    __shared__ float sBt[32][136];   // k-major B
    int tid = threadIdx.x;
    int jstep = blockIdx.x;          // 0..30 == time index
    int r0 = jstep*64;
    int v0 = blockIdx.y*128;
    int tx = tid & 15, ty = tid >> 4;
    unsigned long long acc[4][4];
    #pragma unroll
    for (int i = 0; i < 4; i++)
        #pragma unroll
        for (int j = 0; j < 4; j++) acc[i][j] = 0ull;

    for (int kc = 0; kc < EM; kc += 32){
        for (int e = tid; e < 64*32; e += 256){
            int row = e >> 5, col = e & 31;
            sAt[col][row] = g_E[(size_t)(r0 + row)*EM + kc + col];
        }
        for (int e = tid; e < 128*32; e += 256){
            int row = e >> 5, col = e & 31;
            int v = v0 + row;
            sBt[col][row] = (v < VOC) ? embed[(size_t)v*EM + kc + col] : 0.f;
        }
        __syncthreads();
        #pragma unroll
        for (int k = 0; k < 32; k++){
            const float* bp = &sBt[k][tx*8];
            float4 bv0 = *(const float4*)bp;
            float4 bv1 = *(const float4*)(bp + 4);
            unsigned long long bb[4] = { pack2(bv0.x, bv0.y), pack2(bv0.z, bv0.w),
                                         pack2(bv1.x, bv1.y), pack2(bv1.z, bv1.w) };
            float4 a4 = *(const float4*)&sAt[k][ty*4];
            float af[4] = {a4.x, a4.y, a4.z, a4.w};
            #pragma unroll
            for (int i = 0; i < 4; i++){
                unsigned long long ad = pack2(af[i], af[i]);
                #pragma unroll
                for (int j = 0; j < 4; j++) fma2(acc[i][j], ad, bb[j]);
            }
        }
        __syncthreads();
    }
    int v = v0 + tx*8;
    if (v < VOC){
        #pragma unroll
        for (int i = 0; i < 4; i++){
            int b = ty*4 + i;
            float* op = out + ((size_t)b*Ss + jstep)*VOC + v;
            float2 p0 = unpack2(acc[i][0]), p1 = unpack2(acc[i][1]);
            float2 p2 = unpack2(acc[i][2]), p3 = unpack2(acc[i][3]);
            float4 o0 = {p0.x, p0.y, p1.x, p1.y};
            float4 o1 = {p2.x, p2.y, p3.x, p3.y};
            *(float4*)op = o0;
            *(float4*)(op + 4) = o1;
        }
    }
}

// ---------------- launch ----------------
extern "C" void kernel_launch(void* const* d_in, const int* in_sizes, int n_in,
                              void* d_out, int out_size){
    const float* V     = (const float*)d_in[0];
    const int*   y     = (const int*)  d_in[1];
    const float* embed = (const float*)d_in[2];
    const float* Ww    = (const float*)d_in[3];
    const float* Wb    = (const float*)d_in[4];
    const float* Uw    = (const float*)d_in[5];
    const float* Ub    = (const float*)d_in[6];
    const float* vw    = (const float*)d_in[7];
    const float* vb    = (const float*)d_in[8];
    const float* Wih   = (const float*)d_in[9];
    const float* Whh   = (const float*)d_in[10];
    const float* bih   = (const float*)d_in[11];
    const float* bhh   = (const float*)d_in[12];
    const float* projw = (const float*)d_in[13];
    float* out = (float*)d_out;

    init_kernel<<<Bz*HD/256, 256>>>();
    gather_kernel<<<dim3(Ss, Bz), EM>>>(y, embed);
    uv_kernel<<<dim3(Bz, 7), 256>>>(V, Uw, Ub);

    for (int j = 0; j < Ss; j++){
        int p = j & 1;
        wh_kernel<<<dim3(8, 8), 256>>>(Ww, Wb, p);
        attn_kernel<<<Bz, 256>>>(vw, vb, V);
        lstm_kernel<<<dim3(4, 16), 256>>>(Wih, Whh, bih, bhh, j, p);
    }

    proj_kernel<<<dim3(Ss, 4), 256>>>(projw);
    logit_kernel<<<dim3(Ss, (VOC + 127)/128), 256>>>(embed, out);
}

// round 2
// speedup vs baseline: 1.6884x; 1.6884x over previous
#include <cuda_runtime.h>
#include <math.h>

#define Bz 64
#define Nn 196
#define Tt 32
#define Ss 31
#define VD 128
#define EM 256
#define AT 256
#define HD 512
#define VOC 30000
#define VOCP 30080
#define KX 384      // EM + VD
#define KG 896      // EM + VD + HD
#define JG 2048     // 4*HD
#define RTOT 1984   // Ss*Bz
#define RP 2048

typedef unsigned long long ULL;

// ---------------- scratch (device globals; no allocation) ----------------
__device__ float g_UV[Bz*Nn*AT];        // 12.8 MB
__device__ float g_X[Ss*Bz*EM];
__device__ float g_h[2][Bz*HD];
__device__ float g_c[2][Bz*HD];
__device__ float g_ctx[Bz*VD];
__device__ float g_H[Ss*Bz*HD];
__device__ float g_ET[EM*RP];           // E transposed [k][r], padded rows stay 0
__device__ float g_WwT[HD*AT];          // Ww transposed [k][a]
__device__ float g_WgT[KG*JG];          // [Wih|Whh] transposed [k][j]
__device__ float g_gb[JG];              // bih + bhh
__device__ float g_embedT[EM*VOCP];     // embed transposed [k][v], padded v zeros

// ---------------- packed f32x2 helpers ----------------
__device__ __forceinline__ ULL pack2(float x, float y){
    ULL r; asm("mov.b64 %0, {%1, %2};" : "=l"(r) : "f"(x), "f"(y)); return r;
}
__device__ __forceinline__ float2 unpack2(ULL v){
    float2 r; asm("mov.b64 {%0, %1}, %2;" : "=f"(r.x), "=f"(r.y) : "l"(v)); return r;
}
__device__ __forceinline__ void fma2(ULL& d, ULL a, ULL b){
    asm("fma.rn.f32x2 %0, %1, %2, %0;" : "+l"(d) : "l"(a), "l"(b));
}
__device__ __forceinline__ float sigf(float x){ return __fdividef(1.0f, 1.0f + __expf(-x)); }
__device__ __forceinline__ float tanha(float x){   // fast MUFU tanh (attention only)
    float r; asm("tanh.approx.f32 %0, %1;" : "=f"(r) : "f"(x)); return r;
}
__device__ __forceinline__ float tanhacc(float x){ // accurate-ish tanh for LSTM state
    return __fdividef(2.0f, 1.0f + __expf(-2.0f*x)) - 1.0f;
}

// ---------------- init ----------------
__global__ void init_kernel(){
    int i = blockIdx.x*256 + threadIdx.x;
    g_h[0][i] = 0.f;
    g_c[0][i] = 0.f;
}

// ---------------- one-time transposes ----------------
__global__ void transpose_embed_kernel(const float* __restrict__ embed){
    __shared__ float t[32][33];
    int v0 = blockIdx.x*32, k0 = blockIdx.y*32;
    int tx = threadIdx.x, ty = threadIdx.y;
    #pragma unroll
    for (int i = 0; i < 4; i++){
        int v = v0 + ty + i*8;
        t[ty + i*8][tx] = (v < VOC) ? embed[(size_t)v*EM + k0 + tx] : 0.f;
    }
    __syncthreads();
    #pragma unroll
    for (int i = 0; i < 4; i++){
        g_embedT[(size_t)(k0 + ty + i*8)*VOCP + v0 + tx] = t[tx][ty + i*8];
    }
}

__global__ void transpose_wg_kernel(const float* __restrict__ Wih,
                                    const float* __restrict__ Whh){
    __shared__ float t[32][33];
    int j0 = blockIdx.x*32, k0 = blockIdx.y*32;
    int tx = threadIdx.x, ty = threadIdx.y;
    #pragma unroll
    for (int i = 0; i < 4; i++){
        int j = j0 + ty + i*8;
        int k = k0 + tx;
        float w = (k < KX) ? Wih[(size_t)j*KX + k] : Whh[(size_t)j*HD + (k - KX)];
        t[ty + i*8][tx] = w;
    }
    __syncthreads();
    #pragma unroll
    for (int i = 0; i < 4; i++){
        g_WgT[(size_t)(k0 + ty + i*8)*JG + j0 + tx] = t[tx][ty + i*8];
    }
}

__global__ void transpose_ww_kernel(const float* __restrict__ Ww,
                                    const float* __restrict__ bih,
                                    const float* __restrict__ bhh){
    __shared__ float t[32][33];
    int a0 = blockIdx.x*32, k0 = blockIdx.y*32;
    int tx = threadIdx.x, ty = threadIdx.y;
    #pragma unroll
    for (int i = 0; i < 4; i++){
        t[ty + i*8][tx] = Ww[(size_t)(a0 + ty + i*8)*HD + k0 + tx];
    }
    __syncthreads();
    #pragma unroll
    for (int i = 0; i < 4; i++){
        g_WwT[(size_t)(k0 + ty + i*8)*AT + a0 + tx] = t[tx][ty + i*8];
    }
    // fold in the bias prep (grid covers 8*16=128 blocks; use first 8)
    if (blockIdx.y == 0){
        int base = blockIdx.x * 256 + threadIdx.y*32 + threadIdx.x;
        if (base < JG) g_gb[base] = bih[base] + bhh[base];
    }
}

// ---------------- gather ----------------
__global__ void gather_kernel(const int* __restrict__ y, const float* __restrict__ embed){
    int s = blockIdx.x, b = blockIdx.y, e = threadIdx.x;
    int tok = y[b*Tt + s];
    g_X[(s*Bz + b)*EM + e] = embed[(size_t)tok*EM + e];
}

// ---------------- UV ----------------
__global__ void __launch_bounds__(256) uv_kernel(const float* __restrict__ V,
                                                 const float* __restrict__ Uw,
                                                 const float* __restrict__ Ub){
    int b = blockIdx.x;
    int n0 = blockIdx.y * 32;
    int tid = threadIdx.x;
    __shared__ float sV[32][VD];
    for (int e = tid; e < 32*VD; e += 256){
        int n = n0 + (e / VD);
        sV[e / VD][e % VD] = (n < Nn) ? V[((size_t)b*Nn + n)*VD + (e % VD)] : 0.f;
    }
    __syncthreads();
    int a = tid;
    float acc[32];
    #pragma unroll
    for (int n = 0; n < 32; n++) acc[n] = 0.f;
    for (int kc = 0; kc < VD; kc += 16){
        float u[16];
        #pragma unroll
        for (int i = 0; i < 16; i += 4)
            *(float4*)&u[i] = *(const float4*)&Uw[a*VD + kc + i];
        #pragma unroll
        for (int n = 0; n < 32; n++){
            #pragma unroll
            for (int k = 0; k < 16; k++)
                acc[n] += u[k] * sV[n][kc + k];
        }
    }
    float ub = Ub[a];
    #pragma unroll
    for (int n = 0; n < 32; n++){
        int nn = n0 + n;
        if (nn < Nn) g_UV[((size_t)b*Nn + nn)*AT + a] = acc[n] + ub;
    }
}

// ---------------- fused attention step: Wh + e + softmax + ctx. grid 64, 512 thr ----------------
__global__ void __launch_bounds__(512) attn_kernel(const float* __restrict__ Wb,
                                                   const float* __restrict__ vw,
                                                   const float* __restrict__ vb,
                                                   const float* __restrict__ V,
                                                   int p){
    __shared__ float sW[32*256];     // 32KB staged WwT chunk [kk][a]
    __shared__ float sh[HD];
    __shared__ float sWh[AT];
    __shared__ float sP[2][AT];
    __shared__ float sv[AT];
    __shared__ float se[Nn];
    __shared__ float sctx[4][VD];
    __shared__ float sred[16];
    __shared__ float s_sc[2];

    int b = blockIdx.x, tid = threadIdx.x;
    sh[tid & 511] = g_h[p][b*HD + tid];          // 512 threads, HD=512
    if (tid < AT) sv[tid] = vw[tid];
    __syncthreads();

    // ---- Phase 1: Wh[a] = sum_k h[k]*WwT[k][a] (k split in 2 halves over thread groups)
    int a = tid & 255, kp = tid >> 8;
    float acc = 0.f;
    const float4* wsrc = (const float4*)g_WwT;
    float4 r0 = wsrc[tid], r1 = wsrc[tid + 512], r2 = wsrc[tid + 1024], r3 = wsrc[tid + 1536];
    for (int c = 0; c < 16; c++){
        float4* sw4 = (float4*)sW;
        sw4[tid] = r0; sw4[tid + 512] = r1; sw4[tid + 1024] = r2; sw4[tid + 1536] = r3;
        __syncthreads();
        if (c < 15){
            int base = (c + 1)*2048;
            r0 = wsrc[base + tid];       r1 = wsrc[base + tid + 512];
            r2 = wsrc[base + tid + 1024]; r3 = wsrc[base + tid + 1536];
        }
        if ((c >> 3) == kp){
            int kb = c*32;
            #pragma unroll
            for (int kk = 0; kk < 32; kk++)
                acc += sh[kb + kk] * sW[kk*256 + a];
        }
        __syncthreads();
    }
    sP[kp][a] = acc;
    __syncthreads();
    if (tid < AT) sWh[tid] = sP[0][tid] + sP[1][tid] + Wb[tid];
    __syncthreads();

    // ---- Phase 2: e_n = v . tanh(Wh + UV[n]) + vb
    int warp = tid >> 5, lane = tid & 31;
    float vbias = vb[0];
    for (int n = warp; n < Nn; n += 16){
        const float* uvp = g_UV + ((size_t)b*Nn + n)*AT;
        float pz = 0.f;
        #pragma unroll
        for (int j = 0; j < 8; j++){
            int aa = lane + j*32;
            pz += tanha(sWh[aa] + uvp[aa]) * sv[aa];
        }
        #pragma unroll
        for (int o = 16; o; o >>= 1) pz += __shfl_xor_sync(0xffffffffu, pz, o);
        if (lane == 0) se[n] = pz + vbias;
    }
    __syncthreads();

    // ---- Phase 3: softmax over n
    float m = -1e30f;
    for (int n = tid; n < Nn; n += 512) m = fmaxf(m, se[n]);
    #pragma unroll
    for (int o = 16; o; o >>= 1) m = fmaxf(m, __shfl_xor_sync(0xffffffffu, m, o));
    if (lane == 0) sred[warp] = m;
    __syncthreads();
    if (tid == 0){
        float mm = sred[0];
        #pragma unroll
        for (int i = 1; i < 16; i++) mm = fmaxf(mm, sred[i]);
        s_sc[0] = mm;
    }
    __syncthreads();
    float mm = s_sc[0];
    float sum = 0.f;
    for (int n = tid; n < Nn; n += 512){
        float ex = __expf(se[n] - mm);
        se[n] = ex;
        sum += ex;
    }
    #pragma unroll
    for (int o = 16; o; o >>= 1) sum += __shfl_xor_sync(0xffffffffu, sum, o);
    if (lane == 0) sred[warp] = sum;
    __syncthreads();
    if (tid == 0){
        float s = 0.f;
        #pragma unroll
        for (int i = 0; i < 16; i++) s += sred[i];
        s_sc[1] = 1.0f / s;
    }
    __syncthreads();

    // ---- Phase 4: ctx[d] = (sum_n se[n]*V[b,n,d]) * inv
    float inv = s_sc[1];
    int d = tid & 127, np = tid >> 7;
    float cv = 0.f;
    for (int n = np; n < Nn; n += 4)
        cv += se[n] * V[((size_t)b*Nn + n)*VD + d];
    sctx[np][d] = cv;
    __syncthreads();
    if (tid < VD){
        g_ctx[b*VD + tid] = (sctx[0][tid] + sctx[1][tid] + sctx[2][tid] + sctx[3][tid]) * inv;
    }
}

// ---------------- LSTM step: gates GEMM + pointwise. grid (2,64), 256 thr ----------------
__global__ void __launch_bounds__(256) lstm_kernel(int step, int p){
    __shared__ float sA[32][36];     // [b_local][k]
    __shared__ float sWt[32][36];    // [k][lr]  lr = g*8 + uu
    __shared__ float sG[32][32];     // gate exchange

    int tid = threadIdx.x;
    int b0 = blockIdx.x*32;
    int u0 = blockIdx.y*8;
    const float* hp = g_h[p];
    const float* xp = g_X + (size_t)step*Bz*EM;

    int bt = tid >> 3;       // 0..31
    int jt = tid & 7;        // lr quad = jt*4
    ULL acc0 = 0ull, acc1 = 0ull;

    for (int kc = 0; kc < KG; kc += 32){
        #pragma unroll
        for (int it = 0; it < 4; it++){
            int f = tid + it*256;
            // A tile
            {
                int b_l = f >> 5, kk = f & 31;
                int k = kc + kk, bb = b0 + b_l;
                float v;
                if (k < EM)      v = xp[bb*EM + k];
                else if (k < KX) v = g_ctx[bb*VD + (k - EM)];
                else             v = hp[bb*HD + (k - KX)];
                sA[b_l][kk] = v;
            }
            // W tile (k-major global -> k-major smem)
            {
                int k = f >> 5, lr = f & 31;
                int g = lr >> 3, uu = lr & 7;
                sWt[k][lr] = g_WgT[(size_t)(kc + k)*JG + g*HD + u0 + uu];
            }
        }
        __syncthreads();
        #pragma unroll
        for (int k = 0; k < 32; k += 4){
            float4 av = *(const float4*)&sA[bt][k];
            ulonglong2 w0 = *(const ulonglong2*)&sWt[k  ][jt*4];
            ulonglong2 w1 = *(const ulonglong2*)&sWt[k+1][jt*4];
            ulonglong2 w2 = *(const ulonglong2*)&sWt[k+2][jt*4];
            ulonglong2 w3 = *(const ulonglong2*)&sWt[k+3][jt*4];
            ULL a0 = pack2(av.x, av.x), a1 = pack2(av.y, av.y);
            ULL a2 = pack2(av.z, av.z), a3 = pack2(av.w, av.w);
            fma2(acc0, a0, w0.x); fma2(acc1, a0, w0.y);
            fma2(acc0, a1, w1.x); fma2(acc1, a1, w1.y);
            fma2(acc0, a2, w2.x); fma2(acc1, a2, w2.y);
            fma2(acc0, a3, w3.x); fma2(acc1, a3, w3.y);
        }
        __syncthreads();
    }

    // gate exchange
    float2 v01 = unpack2(acc0), v23 = unpack2(acc1);
    sG[bt][jt*4 + 0] = v01.x;
    sG[bt][jt*4 + 1] = v01.y;
    sG[bt][jt*4 + 2] = v23.x;
    sG[bt][jt*4 + 3] = v23.y;
    __syncthreads();

    int b_l = tid >> 3, uu = tid & 7;
    int bb = b0 + b_l, u = u0 + uu;
    float iv = sG[b_l][ 0 + uu] + g_gb[u];
    float fv = sG[b_l][ 8 + uu] + g_gb[HD + u];
    float gv = sG[b_l][16 + uu] + g_gb[2*HD + u];
    float ov = sG[b_l][24 + uu] + g_gb[3*HD + u];
    float cp = g_c[p][bb*HD + u];
    float cn = sigf(fv)*cp + sigf(iv)*tanhacc(gv);
    float hn = sigf(ov)*tanhacc(cn);
    int q = p ^ 1;
    g_c[q][bb*HD + u] = cn;
    g_h[q][bb*HD + u] = hn;
    g_H[((size_t)step*Bz + bb)*HD + u] = hn;
}

// ---------------- proj: ET[a][r] = (H @ proj.T)^T. grid (31,4), 256 thr ----------------
__global__ void __launch_bounds__(256) proj_kernel(const float* __restrict__ projw){
    __shared__ float sA[64][33];
    __shared__ float sW[64][33];
    int tid = threadIdx.x;
    int r0 = blockIdx.x*64, a0 = blockIdx.y*64;
    int tx = tid & 15, ty = tid >> 4;
    float acc[4][4] = {};
    for (int kc = 0; kc < HD; kc += 32){
        for (int e = tid; e < 64*32; e += 256){
            int row = e >> 5, col = e & 31;
            sA[row][col] = g_H[(size_t)(r0 + row)*HD + kc + col];
            sW[row][col] = projw[(size_t)(a0 + row)*HD + kc + col];
        }
        __syncthreads();
        #pragma unroll
        for (int k = 0; k < 32; k++){
            float af[4], wf[4];
            #pragma unroll
            for (int i = 0; i < 4; i++) af[i] = sA[ty*4 + i][k];
            #pragma unroll
            for (int j = 0; j < 4; j++) wf[j] = sW[tx*4 + j][k];
            #pragma unroll
            for (int i = 0; i < 4; i++)
                #pragma unroll
                for (int j = 0; j < 4; j++)
                    acc[i][j] += af[i]*wf[j];
        }
        __syncthreads();
    }
    #pragma unroll
    for (int i = 0; i < 4; i++)
        #pragma unroll
        for (int j = 0; j < 4; j++)
            g_ET[(size_t)(a0 + tx*4 + j)*RP + (r0 + ty*4 + i)] = acc[i][j];
}

// ---------------- logits: 128x128 tile, 8x8 per thread, f32x2. grid (16,235) ----------------
__global__ void __launch_bounds__(256) logit_kernel(float* __restrict__ out){
    __shared__ float sAk[32][132];   // [k][r]
    __shared__ float sBk[32][132];   // [k][v]
    int tid = threadIdx.x;
    int r0 = blockIdx.x*128;
    int v0 = blockIdx.y*128;
    int tx = tid & 15, ty = tid >> 4;

    ULL acc[8][4];
    #pragma unroll
    for (int i = 0; i < 8; i++)
        #pragma unroll
        for (int j = 0; j < 4; j++) acc[i][j] = 0ull;

    for (int kc = 0; kc < EM; kc += 32){
        #pragma unroll
        for (int it = 0; it < 4; it++){
            int f = tid + it*256;
            int k = f >> 5, q = f & 31;
            float4 va = *(const float4*)&g_ET[(size_t)(kc + k)*RP + r0 + q*4];
            *(float4*)&sAk[k][q*4] = va;
            float4 vbv = *(const float4*)&g_embedT[(size_t)(kc + k)*VOCP + v0 + q*4];
            *(float4*)&sBk[k][q*4] = vbv;
        }
        __syncthreads();
        #pragma unroll
        for (int k = 0; k < 32; k++){
            float4 A0 = *(const float4*)&sAk[k][ty*8];
            float4 A1 = *(const float4*)&sAk[k][ty*8 + 4];
            ulonglong2 B0 = *(const ulonglong2*)&sBk[k][tx*8];
            ulonglong2 B1 = *(const ulonglong2*)&sBk[k][tx*8 + 4];
            float af[8] = {A0.x, A0.y, A0.z, A0.w, A1.x, A1.y, A1.z, A1.w};
            #pragma unroll
            for (int i = 0; i < 8; i++){
                ULL ad = pack2(af[i], af[i]);
                fma2(acc[i][0], ad, B0.x);
                fma2(acc[i][1], ad, B0.y);
                fma2(acc[i][2], ad, B1.x);
                fma2(acc[i][3], ad, B1.y);
            }
        }
        __syncthreads();
    }

    int vbase = v0 + tx*8;
    bool vok = (vbase < VOC);   // 30000 % 8 == 0, so whole 8-group in or out
    #pragma unroll
    for (int i = 0; i < 8; i++){
        int r = r0 + ty*8 + i;
        if (r < RTOT && vok){
            int st = r >> 6, bb = r & 63;
            float* op = out + ((size_t)bb*Ss + st)*VOC + vbase;
            float2 p0 = unpack2(acc[i][0]), p1 = unpack2(acc[i][1]);
            float2 p2 = unpack2(acc[i][2]), p3 = unpack2(acc[i][3]);
            float4 o0 = {p0.x, p0.y, p1.x, p1.y};
            float4 o1 = {p2.x, p2.y, p3.x, p3.y};
            *(float4*)op = o0;
            *(float4*)(op + 4) = o1;
        }
    }
}

// ---------------- launch ----------------
extern "C" void kernel_launch(void* const* d_in, const int* in_sizes, int n_in,
                              void* d_out, int out_size){
    const float* V     = (const float*)d_in[0];
    const int*   y     = (const int*)  d_in[1];
    const float* embed = (const float*)d_in[2];
    const float* Ww    = (const float*)d_in[3];
    const float* Wb    = (const float*)d_in[4];
    const float* Uw    = (const float*)d_in[5];
    const float* Ub    = (const float*)d_in[6];
    const float* vw    = (const float*)d_in[7];
    const float* vb    = (const float*)d_in[8];
    const float* Wih   = (const float*)d_in[9];
    const float* Whh   = (const float*)d_in[10];
    const float* bih   = (const float*)d_in[11];
    const float* bhh   = (const float*)d_in[12];
    const float* projw = (const float*)d_in[13];
    float* out = (float*)d_out;

    init_kernel<<<Bz*HD/256, 256>>>();
    transpose_embed_kernel<<<dim3((VOC + 31)/32, EM/32), dim3(32, 8)>>>(embed);
    transpose_wg_kernel<<<dim3(JG/32, KG/32), dim3(32, 8)>>>(Wih, Whh);
    transpose_ww_kernel<<<dim3(AT/32, HD/32), dim3(32, 8)>>>(Ww, bih, bhh);
    gather_kernel<<<dim3(Ss, Bz), EM>>>(y, embed);
    uv_kernel<<<dim3(Bz, 7), 256>>>(V, Uw, Ub);

    for (int j = 0; j < Ss; j++){
        int p = j & 1;
        attn_kernel<<<Bz, 512>>>(Wb, vw, vb, V, p);
        lstm_kernel<<<dim3(2, 64), 256>>>(j, p);
    }

    proj_kernel<<<dim3(Ss, 4), 256>>>(projw);
    logit_kernel<<<dim3(16, (VOC + 127)/128), 256>>>(out);
}

// round 5
// speedup vs baseline: 2.8291x; 1.6757x over previous
#include <cuda_runtime.h>
#include <cuda_bf16.h>
#include <math.h>
#include <cstdint>

#define Bz 64
#define Nn 196
#define Tt 32
#define Ss 31
#define VD 128
#define EM 256
#define AT 256
#define HD 512
#define VOC 30000
#define VOCP 30080
#define KX 384      // EM + VD
#define KG 896      // EM + VD + HD
#define JG 2048     // 4*HD
#define RTOT 1984   // Ss*Bz
#define RP 2048
#define K2 768      // split-concat K: A=[hi|hi|lo] x B=[hi|lo|hi]

typedef unsigned long long ULL;

// ---------------- scratch (device globals; zero-initialized, no allocation) ----------------
__device__ float g_UV[Bz*Nn*AT];
__device__ float g_X[Ss*Bz*EM];
__device__ float g_h[2][Bz*HD];
__device__ float g_c[2][Bz*HD];
__device__ float g_ctx[Bz*VD];
__device__ float g_H[Ss*Bz*HD];
__device__ float g_WwT[HD*AT];                 // Ww transposed [k][a]
__device__ float g_WgT[KG*JG];                 // [Wih|Whh] transposed [k][j]
__device__ float g_gb[JG];                     // bih + bhh
__device__ __nv_bfloat16 g_A2[RP*K2];          // E split-concat rows [hi|hi|lo]; pad rows stay 0
__device__ __nv_bfloat16 g_B2[VOCP*K2];        // embed split-concat rows [hi|lo|hi]; pad rows stay 0

// ---------------- packed f32x2 helpers ----------------
__device__ __forceinline__ ULL pack2(float x, float y){
    ULL r; asm("mov.b64 %0, {%1, %2};" : "=l"(r) : "f"(x), "f"(y)); return r;
}
__device__ __forceinline__ float2 unpack2(ULL v){
    float2 r; asm("mov.b64 {%0, %1}, %2;" : "=f"(r.x), "=f"(r.y) : "l"(v)); return r;
}
__device__ __forceinline__ void fma2(ULL& d, ULL a, ULL b){
    asm("fma.rn.f32x2 %0, %1, %2, %0;" : "+l"(d) : "l"(a), "l"(b));
}
__device__ __forceinline__ float sigf(float x){ return __fdividef(1.0f, 1.0f + __expf(-x)); }
__device__ __forceinline__ float tanha(float x){
    float r; asm("tanh.approx.f32 %0, %1;" : "=f"(r) : "f"(x)); return r;
}
__device__ __forceinline__ float tanhacc(float x){
    return __fdividef(2.0f, 1.0f + __expf(-2.0f*x)) - 1.0f;
}

// ---------------- mma.sync / ldmatrix / cp.async helpers (compute_103-safe) ----------------
__device__ __forceinline__ uint32_t smem_to_u32(const void* smem_ptr){
    uint32_t addr;
    asm("{ .reg .u64 tmp; cvta.to.shared.u64 tmp, %1; cvt.u32.u64 %0, tmp; }"
        : "=r"(addr) : "l"(smem_ptr));
    return addr;
}
#define SWZ(o) ((o) ^ (((o) >> 3) & 0x70))

__device__ __forceinline__ void ldmatrix_x4(uint32_t& r0, uint32_t& r1, uint32_t& r2, uint32_t& r3,
                                            uint32_t addr){
    asm volatile("ldmatrix.sync.aligned.m8n8.x4.shared.b16 {%0,%1,%2,%3}, [%4];"
                 : "=r"(r0), "=r"(r1), "=r"(r2), "=r"(r3) : "r"(addr));
}
__device__ __forceinline__ void mma16816(float* d, const uint32_t* a, uint32_t b0, uint32_t b1){
    asm volatile("mma.sync.aligned.m16n8k16.row.col.f32.bf16.bf16.f32 "
                 "{%0,%1,%2,%3}, {%4,%5,%6,%7}, {%8,%9}, {%0,%1,%2,%3};"
                 : "+f"(d[0]), "+f"(d[1]), "+f"(d[2]), "+f"(d[3])
                 : "r"(a[0]), "r"(a[1]), "r"(a[2]), "r"(a[3]), "r"(b0), "r"(b1));
}
__device__ __forceinline__ void cp_async16(uint32_t dst, const void* src){
    asm volatile("cp.async.cg.shared.global [%0], [%1], 16;" :: "r"(dst), "l"(src) : "memory");
}

// ---------------- embed -> split-concat bf16 rows: B = [hi|lo|hi] ----------------
__global__ void __launch_bounds__(256) conv_embed_kernel(const float* __restrict__ embed){
    size_t i = ((size_t)blockIdx.x*256 + threadIdx.x)*4;   // global element idx, 4/thread
    size_t v = i / EM;
    int k = (int)(i % EM);
    float4 x = *(const float4*)(embed + i);
    float xs[4] = {x.x, x.y, x.z, x.w};
    unsigned short h[4], l[4];
    #pragma unroll
    for (int j = 0; j < 4; j++){
        __nv_bfloat16 hb = __float2bfloat16(xs[j]);
        float lo = xs[j] - __bfloat162float(hb);
        __nv_bfloat16 lb = __float2bfloat16(lo);
        h[j] = __bfloat16_as_ushort(hb);
        l[j] = __bfloat16_as_ushort(lb);
    }
    uint2 hv, lv;
    hv.x = (uint32_t)h[0] | ((uint32_t)h[1] << 16);
    hv.y = (uint32_t)h[2] | ((uint32_t)h[3] << 16);
    lv.x = (uint32_t)l[0] | ((uint32_t)l[1] << 16);
    lv.y = (uint32_t)l[2] | ((uint32_t)l[3] << 16);
    __nv_bfloat16* row = g_B2 + v*K2;
    *(uint2*)(row + k)       = hv;   // hi
    *(uint2*)(row + 256 + k) = lv;   // lo
    *(uint2*)(row + 512 + k) = hv;   // hi
}

// ---------------- one-time transposes ----------------
__global__ void transpose_wg_kernel(const float* __restrict__ Wih,
                                    const float* __restrict__ Whh){
    __shared__ float t[32][33];
    int j0 = blockIdx.x*32, k0 = blockIdx.y*32;
    int tx = threadIdx.x, ty = threadIdx.y;
    #pragma unroll
    for (int i = 0; i < 4; i++){
        int j = j0 + ty + i*8;
        int k = k0 + tx;
        float w = (k < KX) ? Wih[(size_t)j*KX + k] : Whh[(size_t)j*HD + (k - KX)];
        t[ty + i*8][tx] = w;
    }
    __syncthreads();
    #pragma unroll
    for (int i = 0; i < 4; i++){
        g_WgT[(size_t)(k0 + ty + i*8)*JG + j0 + tx] = t[tx][ty + i*8];
    }
}

// transpose Ww + fold bias prep + zero h0/c0
__global__ void transpose_ww_kernel(const float* __restrict__ Ww,
                                    const float* __restrict__ bih,
                                    const float* __restrict__ bhh){
    __shared__ float t[32][33];
    int a0 = blockIdx.x*32, k0 = blockIdx.y*32;
    int tx = threadIdx.x, ty = threadIdx.y;
    #pragma unroll
    for (int i = 0; i < 4; i++){
        t[ty + i*8][tx] = Ww[(size_t)(a0 + ty + i*8)*HD + k0 + tx];
    }
    __syncthreads();
    #pragma unroll
    for (int i = 0; i < 4; i++){
        g_WwT[(size_t)(k0 + ty + i*8)*AT + a0 + tx] = t[tx][ty + i*8];
    }
    if (blockIdx.y == 0){
        int base = blockIdx.x*256 + threadIdx.y*32 + threadIdx.x;
        if (base < JG) g_gb[base] = bih[base] + bhh[base];
    }
    // zero h0/c0: 128 blocks * 256 threads == 32768 == Bz*HD
    int zi = (blockIdx.y*8 + blockIdx.x)*256 + threadIdx.y*32 + threadIdx.x;
    g_h[0][zi] = 0.f;
    g_c[0][zi] = 0.f;
}

// ---------------- gather ----------------
__global__ void gather_kernel(const int* __restrict__ y, const float* __restrict__ embed){
    int s = blockIdx.x, b = blockIdx.y, e = threadIdx.x;
    int tok = y[b*Tt + s];
    g_X[(s*Bz + b)*EM + e] = embed[(size_t)tok*EM + e];
}

// ---------------- UV ----------------
__global__ void __launch_bounds__(256) uv_kernel(const float* __restrict__ V,
                                                 const float* __restrict__ Uw,
                                                 const float* __restrict__ Ub){
    int b = blockIdx.x;
    int n0 = blockIdx.y * 32;
    int tid = threadIdx.x;
    __shared__ float sV[32][VD];
    for (int e = tid; e < 32*VD; e += 256){
        int n = n0 + (e / VD);
        sV[e / VD][e % VD] = (n < Nn) ? V[((size_t)b*Nn + n)*VD + (e % VD)] : 0.f;
    }
    __syncthreads();
    int a = tid;
    float acc[32];
    #pragma unroll
    for (int n = 0; n < 32; n++) acc[n] = 0.f;
    for (int kc = 0; kc < VD; kc += 16){
        float u[16];
        #pragma unroll
        for (int i = 0; i < 16; i += 4)
            *(float4*)&u[i] = *(const float4*)&Uw[a*VD + kc + i];
        #pragma unroll
        for (int n = 0; n < 32; n++){
            #pragma unroll
            for (int k = 0; k < 16; k++)
                acc[n] += u[k] * sV[n][kc + k];
        }
    }
    float ub = Ub[a];
    #pragma unroll
    for (int n = 0; n < 32; n++){
        int nn = n0 + n;
        if (nn < Nn) g_UV[((size_t)b*Nn + nn)*AT + a] = acc[n] + ub;
    }
}

// ---------------- fused attention step ----------------
__global__ void __launch_bounds__(512) attn_kernel(const float* __restrict__ Wb,
                                                   const float* __restrict__ vw,
                                                   const float* __restrict__ vb,
                                                   const float* __restrict__ V,
                                                   int p){
    __shared__ float sW[32*256];
    __shared__ float sh[HD];
    __shared__ float sWh[AT];
    __shared__ float sP[2][AT];
    __shared__ float sv[AT];
    __shared__ float se[Nn];
    __shared__ float sctx[4][VD];
    __shared__ float sred[16];
    __shared__ float s_sc[2];

    int b = blockIdx.x, tid = threadIdx.x;
    sh[tid & 511] = g_h[p][b*HD + tid];
    if (tid < AT) sv[tid] = vw[tid];
    __syncthreads();

    int a = tid & 255, kp = tid >> 8;
    float acc = 0.f;
    const float4* wsrc = (const float4*)g_WwT;
    float4 r0 = wsrc[tid], r1 = wsrc[tid + 512], r2 = wsrc[tid + 1024], r3 = wsrc[tid + 1536];
    for (int c = 0; c < 16; c++){
        float4* sw4 = (float4*)sW;
        sw4[tid] = r0; sw4[tid + 512] = r1; sw4[tid + 1024] = r2; sw4[tid + 1536] = r3;
        __syncthreads();
        if (c < 15){
            int base = (c + 1)*2048;
            r0 = wsrc[base + tid];        r1 = wsrc[base + tid + 512];
            r2 = wsrc[base + tid + 1024]; r3 = wsrc[base + tid + 1536];
        }
        if ((c >> 3) == kp){
            int kb = c*32;
            #pragma unroll
            for (int kk = 0; kk < 32; kk++)
                acc += sh[kb + kk] * sW[kk*256 + a];
        }
        __syncthreads();
    }
    sP[kp][a] = acc;
    __syncthreads();
    if (tid < AT) sWh[tid] = sP[0][tid] + sP[1][tid] + Wb[tid];
    __syncthreads();

    int warp = tid >> 5, lane = tid & 31;
    float vbias = vb[0];
    for (int n = warp; n < Nn; n += 16){
        const float* uvp = g_UV + ((size_t)b*Nn + n)*AT;
        float pz = 0.f;
        #pragma unroll
        for (int j = 0; j < 8; j++){
            int aa = lane + j*32;
            pz += tanha(sWh[aa] + uvp[aa]) * sv[aa];
        }
        #pragma unroll
        for (int o = 16; o; o >>= 1) pz += __shfl_xor_sync(0xffffffffu, pz, o);
        if (lane == 0) se[n] = pz + vbias;
    }
    __syncthreads();

    float m = -1e30f;
    for (int n = tid; n < Nn; n += 512) m = fmaxf(m, se[n]);
    #pragma unroll
    for (int o = 16; o; o >>= 1) m = fmaxf(m, __shfl_xor_sync(0xffffffffu, m, o));
    if (lane == 0) sred[warp] = m;
    __syncthreads();
    if (tid == 0){
        float mm = sred[0];
        #pragma unroll
        for (int i = 1; i < 16; i++) mm = fmaxf(mm, sred[i]);
        s_sc[0] = mm;
    }
    __syncthreads();
    float mm = s_sc[0];
    float sum = 0.f;
    for (int n = tid; n < Nn; n += 512){
        float ex = __expf(se[n] - mm);
        se[n] = ex;
        sum += ex;
    }
    #pragma unroll
    for (int o = 16; o; o >>= 1) sum += __shfl_xor_sync(0xffffffffu, sum, o);
    if (lane == 0) sred[warp] = sum;
    __syncthreads();
    if (tid == 0){
        float s = 0.f;
        #pragma unroll
        for (int i = 0; i < 16; i++) s += sred[i];
        s_sc[1] = 1.0f / s;
    }
    __syncthreads();

    float inv = s_sc[1];
    int d = tid & 127, np = tid >> 7;
    float cv = 0.f;
    for (int n = np; n < Nn; n += 4)
        cv += se[n] * V[((size_t)b*Nn + n)*VD + d];
    sctx[np][d] = cv;
    __syncthreads();
    if (tid < VD){
        g_ctx[b*VD + tid] = (sctx[0][tid] + sctx[1][tid] + sctx[2][tid] + sctx[3][tid]) * inv;
    }
}

// ---------------- LSTM step ----------------
__global__ void __launch_bounds__(256) lstm_kernel(int step, int p){
    __shared__ float sA[2][32][68];
    __shared__ float sWt[2][64][36];
    __shared__ float sG[32][32];

    int tid = threadIdx.x;
    int b0 = blockIdx.x*32;
    int u0 = blockIdx.y*8;
    const float* hp = g_h[p];
    const float* xp = g_X + (size_t)step*Bz*EM;

    int bt = tid >> 3;
    int jt = tid & 7;
    ULL acc0 = 0ull, acc1 = 0ull;
    float ra[8], rw[8];

#define LSTM_LOADC(kc) { \
    _Pragma("unroll") \
    for (int it = 0; it < 8; it++){ \
        int f = tid + it*256; \
        int b_l = f >> 6, kk = f & 63; \
        int k = (kc) + kk, bb = b0 + b_l; \
        float v; \
        if (k < EM)      v = xp[bb*EM + k]; \
        else if (k < KX) v = g_ctx[bb*VD + (k - EM)]; \
        else             v = hp[bb*HD + (k - KX)]; \
        ra[it] = v; \
        int k2 = f >> 5, lr = f & 31; \
        rw[it] = g_WgT[(size_t)((kc) + k2)*JG + (lr >> 3)*HD + u0 + (lr & 7)]; \
    } }

#define LSTM_STOREC(buf) { \
    _Pragma("unroll") \
    for (int it = 0; it < 8; it++){ \
        int f = tid + it*256; \
        sA[buf][f >> 6][f & 63] = ra[it]; \
        sWt[buf][f >> 5][f & 31] = rw[it]; \
    } }

    LSTM_LOADC(0);
    LSTM_STOREC(0);
    __syncthreads();

    for (int c = 0; c < 14; c++){
        int buf = c & 1;
        if (c < 13) LSTM_LOADC((c + 1)*64);
        #pragma unroll
        for (int k = 0; k < 64; k += 4){
            float4 av = *(const float4*)&sA[buf][bt][k];
            ulonglong2 w0 = *(const ulonglong2*)&sWt[buf][k  ][jt*4];
            ulonglong2 w1 = *(const ulonglong2*)&sWt[buf][k+1][jt*4];
            ulonglong2 w2 = *(const ulonglong2*)&sWt[buf][k+2][jt*4];
            ulonglong2 w3 = *(const ulonglong2*)&sWt[buf][k+3][jt*4];
            ULL a0 = pack2(av.x, av.x), a1 = pack2(av.y, av.y);
            ULL a2 = pack2(av.z, av.z), a3 = pack2(av.w, av.w);
            fma2(acc0, a0, w0.x); fma2(acc1, a0, w0.y);
            fma2(acc0, a1, w1.x); fma2(acc1, a1, w1.y);
            fma2(acc0, a2, w2.x); fma2(acc1, a2, w2.y);
            fma2(acc0, a3, w3.x); fma2(acc1, a3, w3.y);
        }
        if (c < 13) LSTM_STOREC(buf ^ 1);
        __syncthreads();
    }

    float2 v01 = unpack2(acc0), v23 = unpack2(acc1);
    sG[bt][jt*4 + 0] = v01.x;
    sG[bt][jt*4 + 1] = v01.y;
    sG[bt][jt*4 + 2] = v23.x;
    sG[bt][jt*4 + 3] = v23.y;
    __syncthreads();

    int b_l = tid >> 3, uu = tid & 7;
    int bb = b0 + b_l, u = u0 + uu;
    float iv = sG[b_l][ 0 + uu] + g_gb[u];
    float fv = sG[b_l][ 8 + uu] + g_gb[HD + u];
    float gv = sG[b_l][16 + uu] + g_gb[2*HD + u];
    float ov = sG[b_l][24 + uu] + g_gb[3*HD + u];
    float cp = g_c[p][bb*HD + u];
    float cn = sigf(fv)*cp + sigf(iv)*tanhacc(gv);
    float hn = sigf(ov)*tanhacc(cn);
    int q = p ^ 1;
    g_c[q][bb*HD + u] = cn;
    g_h[q][bb*HD + u] = hn;
    g_H[((size_t)step*Bz + bb)*HD + u] = hn;
}

// ---------------- proj: E = H @ proj.T, epilogue writes split-concat rows A = [hi|hi|lo] ----------------
__global__ void __launch_bounds__(256) proj_kernel(const float* __restrict__ projw){
    __shared__ float sA[64][33];
    __shared__ float sW[64][33];
    int tid = threadIdx.x;
    int r0 = blockIdx.x*64, a0 = blockIdx.y*64;
    int tx = tid & 15, ty = tid >> 4;
    float acc[4][4] = {};
    for (int kc = 0; kc < HD; kc += 32){
        for (int e = tid; e < 64*32; e += 256){
            int row = e >> 5, col = e & 31;
            sA[row][col] = g_H[(size_t)(r0 + row)*HD + kc + col];
            sW[row][col] = projw[(size_t)(a0 + row)*HD + kc + col];
        }
        __syncthreads();
        #pragma unroll
        for (int k = 0; k < 32; k++){
            float af[4], wf[4];
            #pragma unroll
            for (int i = 0; i < 4; i++) af[i] = sA[ty*4 + i][k];
            #pragma unroll
            for (int j = 0; j < 4; j++) wf[j] = sW[tx*4 + j][k];
            #pragma unroll
            for (int i = 0; i < 4; i++)
                #pragma unroll
                for (int j = 0; j < 4; j++)
                    acc[i][j] += af[i]*wf[j];
        }
        __syncthreads();
    }
    #pragma unroll
    for (int i = 0; i < 4; i++){
        int r = r0 + ty*4 + i;
        __nv_bfloat16* row = g_A2 + (size_t)r*K2;
        #pragma unroll
        for (int jp = 0; jp < 2; jp++){
            float x0 = acc[i][jp*2], x1 = acc[i][jp*2 + 1];
            __nv_bfloat16 h0 = __float2bfloat16(x0);
            __nv_bfloat16 h1 = __float2bfloat16(x1);
            __nv_bfloat16 l0 = __float2bfloat16(x0 - __bfloat162float(h0));
            __nv_bfloat16 l1 = __float2bfloat16(x1 - __bfloat162float(h1));
            uint32_t hv = (uint32_t)__bfloat16_as_ushort(h0) | ((uint32_t)__bfloat16_as_ushort(h1) << 16);
            uint32_t lv = (uint32_t)__bfloat16_as_ushort(l0) | ((uint32_t)__bfloat16_as_ushort(l1) << 16);
            int k = a0 + tx*4 + jp*2;
            *(uint32_t*)(row + k)       = hv;   // hi  (pairs with B hi)
            *(uint32_t*)(row + 256 + k) = hv;   // hi  (pairs with B lo)   <-- FIXED
            *(uint32_t*)(row + 512 + k) = lv;   // lo  (pairs with B hi)   <-- FIXED
        }
    }
}

// ---------------- logits: mma.sync bf16 GEMM, K=768, 128x128 tile, cp.async 3-stage ----------------
#define KCH 64
#define STG_BYTES 32768                 // A 16KB + B 16KB per stage
#define LOGIT_SMEM (3*STG_BYTES)        // 96KB

extern __shared__ char lg_smem[];

__global__ void __launch_bounds__(256, 2) logit_mma_kernel(float* __restrict__ out){
    uint32_t sb = smem_to_u32(lg_smem);
    int tid = threadIdx.x;
    int warp = tid >> 5, lane = tid & 31;
    int wm = warp >> 2, wn = warp & 3;
    int r0 = blockIdx.x*128, v0 = blockIdx.y*128;
    const __nv_bfloat16* Ag = g_A2 + (size_t)r0*K2;
    const __nv_bfloat16* Bg = g_B2 + (size_t)v0*K2;

    float acc[4][4][4];
    #pragma unroll
    for (int i = 0; i < 4; i++)
        #pragma unroll
        for (int j = 0; j < 4; j++)
            #pragma unroll
            for (int q = 0; q < 4; q++) acc[i][j][q] = 0.f;

#define LOAD_STAGE(s, kc) { \
    uint32_t base_ = sb + (uint32_t)(s)*STG_BYTES; \
    _Pragma("unroll") \
    for (int it = 0; it < 8; it++){ \
        int f = tid + it*256; \
        int side = f >> 10, idx = f & 1023; \
        int row = idx >> 3, ch = idx & 7; \
        const __nv_bfloat16* src = (side ? Bg : Ag) + (size_t)row*K2 + (kc) + ch*8; \
        uint32_t off = (uint32_t)(side*16384 + SWZ(row*128 + ch*16)); \
        cp_async16(base_ + off, src); \
    } \
    asm volatile("cp.async.commit_group;" ::: "memory"); \
}

    LOAD_STAGE(0, 0);
    LOAD_STAGE(1, KCH);
    LOAD_STAGE(2, 2*KCH);

    int lrow = ((lane >> 3) & 1)*8 + (lane & 7);   // ldmatrix source row within 16-row tile
    int lkb  = (lane >> 4)*16;                     // 16B chunk within k16

    for (int c = 0; c < 12; c++){
        asm volatile("cp.async.wait_group 2;" ::: "memory");
        __syncthreads();
        int s = c % 3;
        uint32_t aBase = sb + (uint32_t)s*STG_BYTES;
        uint32_t bBase = aBase + 16384;
        #pragma unroll
        for (int k16 = 0; k16 < 4; k16++){
            int kb = k16*32 + lkb;
            uint32_t a[4][4], bfr[2][4];
            #pragma unroll
            for (int mi = 0; mi < 4; mi++){
                int row = wm*64 + mi*16 + lrow;
                ldmatrix_x4(a[mi][0], a[mi][1], a[mi][2], a[mi][3],
                            aBase + (uint32_t)SWZ(row*128 + kb));
            }
            #pragma unroll
            for (int nh = 0; nh < 2; nh++){
                int row = wn*32 + nh*16 + lrow;
                ldmatrix_x4(bfr[nh][0], bfr[nh][1], bfr[nh][2], bfr[nh][3],
                            bBase + (uint32_t)SWZ(row*128 + kb));
            }
            #pragma unroll
            for (int mi = 0; mi < 4; mi++)
                #pragma unroll
                for (int nj = 0; nj < 4; nj++)
                    mma16816(acc[mi][nj], a[mi], bfr[nj>>1][nj&1], bfr[nj>>1][(nj&1)+2]);
        }
        __syncthreads();
        if (c + 3 < 12){
            LOAD_STAGE((c + 3) % 3, (c + 3)*KCH);
        } else {
            asm volatile("cp.async.commit_group;" ::: "memory");
        }
    }

    // epilogue: direct stores (pairs); rows map r = s*64 + b
    #pragma unroll
    for (int mi = 0; mi < 4; mi++){
        int rbase = r0 + wm*64 + mi*16 + (lane >> 2);
        #pragma unroll
        for (int half = 0; half < 2; half++){
            int r = rbase + half*8;
            if (r < RTOT){
                int st = r >> 6, bb = r & 63;
                float* op = out + ((size_t)bb*Ss + st)*VOC;
                #pragma unroll
                for (int nj = 0; nj < 4; nj++){
                    int v = v0 + wn*32 + nj*8 + (lane & 3)*2;
                    if (v < VOC){
                        float2 val = {acc[mi][nj][half*2], acc[mi][nj][half*2 + 1]};
                        *(float2*)(op + v) = val;
                    }
                }
            }
        }
    }
#undef LOAD_STAGE
}

// ---------------- launch ----------------
extern "C" void kernel_launch(void* const* d_in, const int* in_sizes, int n_in,
                              void* d_out, int out_size){
    const float* V     = (const float*)d_in[0];
    const int*   y     = (const int*)  d_in[1];
    const float* embed = (const float*)d_in[2];
    const float* Ww    = (const float*)d_in[3];
    const float* Wb    = (const float*)d_in[4];
    const float* Uw    = (const float*)d_in[5];
    const float* Ub    = (const float*)d_in[6];
    const float* vw    = (const float*)d_in[7];
    const float* vb    = (const float*)d_in[8];
    const float* Wih   = (const float*)d_in[9];
    const float* Whh   = (const float*)d_in[10];
    const float* bih   = (const float*)d_in[11];
    const float* bhh   = (const float*)d_in[12];
    const float* projw = (const float*)d_in[13];
    float* out = (float*)d_out;

    cudaFuncSetAttribute(logit_mma_kernel,
                         cudaFuncAttributeMaxDynamicSharedMemorySize, LOGIT_SMEM);

    // order chosen so attn_kernel is launch #4 (ncu profiles it)
    uv_kernel<<<dim3(Bz, 7), 256>>>(V, Uw, Ub);                              // 1
    transpose_ww_kernel<<<dim3(AT/32, HD/32), dim3(32, 8)>>>(Ww, bih, bhh);  // 2 (+init h0/c0)
    conv_embed_kernel<<<(VOC*EM)/(256*4), 256>>>(embed);                     // 3
    attn_kernel<<<Bz, 512>>>(Wb, vw, vb, V, 0);                              // 4 <- profiled
    gather_kernel<<<dim3(Ss, Bz), EM>>>(y, embed);                           // 5
    transpose_wg_kernel<<<dim3(JG/32, KG/32), dim3(32, 8)>>>(Wih, Whh);      // 6
    lstm_kernel<<<dim3(2, 64), 256>>>(0, 0);                                 // 7

    for (int j = 1; j < Ss; j++){
        int p = j & 1;
        attn_kernel<<<Bz, 512>>>(Wb, vw, vb, V, p);
        lstm_kernel<<<dim3(2, 64), 256>>>(j, p);
    }

    proj_kernel<<<dim3(Ss, 4), 256>>>(projw);
    logit_mma_kernel<<<dim3(RP/128, VOCP/128), 256, LOGIT_SMEM>>>(out);
}